// round 11
// baseline (speedup 1.0000x reference)
#include <cuda_runtime.h>
#include <cstdint>

#define KS 93          // gaussian kernel size (static, matches reference)
#define NPTS 256       // points per batch
#define W_OUT 512
#define H_OUT 512
#define RPB 4          // rows per warp tile
#define NT 128         // 4 warps per block; warp w -> 64-col window
#define P 64           // gaussian table base: index for patch offset 0
#define GLEN 220       // table length: nonzero exactly in [P, P+93)

// One block per (batch, 4-row group, 256-col half): grid = 8*128*2 = 2048.
// Warp w owns cols [half*256 + 64w, +64) x 4 rows; lane owns 2 adjacent cols.
// Each warp classifies all 256 points itself -> warp-private compact list.
// Only 2 barriers (shared gaussian tables); no cross-warp data flow after.
__global__ __launch_bounds__(NT)
void density_kernel(const float* __restrict__ labels,
                    const float* __restrict__ sigma_ptr,
                    float* __restrict__ out) {
    const int half    = blockIdx.x & 1;
    const int rowBase = ((blockIdx.x >> 1) & 127) * RPB;
    const int b       = blockIdx.x >> 8;
    const int t    = threadIdx.x;
    const int warp = t >> 5;
    const int lane = t & 31;
    const int cbw  = half * 256 + warp * 64;      // this warp's column base

    __shared__ __align__(8) float2 gpair[GLEN];   // {g[i], g[i+1]}
    __shared__ __align__(8) float2 gdup[GLEN];    // {g[i], g[i]}
    __shared__ int   lists[4][NPTS];              // warp-private compact lists
    __shared__ float wsum[3];

    // ---- Prefetch labels (8 points per lane) + sigma ---------------------
    const float2* lab = (const float2*)(labels + (size_t)b * NPTS * 2);
    float2 pt[8];
    #pragma unroll
    for (int r = 0; r < 8; r++) pt[r] = lab[r * 32 + lane];
    const float s = fabsf(sigma_ptr[0]);
    const float inv2s2 = 1.0f / (2.0f * s * s);

    // ---- Gaussian sum (warps 0-2 hold t<96) ------------------------------
    float gval = 0.0f;
    if (t < KS) {
        const float a = (float)(t - KS / 2);      // [-46, 46]
        gval = __expf(-(a * a) * inv2s2);
    }
    if (warp < 3) {
        float v = gval;
        #pragma unroll
        for (int off = 16; off > 0; off >>= 1) v += __shfl_down_sync(0xffffffffu, v, off);
        if (lane == 0) wsum[warp] = v;
    }
    __syncthreads();                               // B1: wsum ready
    const float invT = 1.0f / (wsum[0] + wsum[1] + wsum[2]);

    // ---- Build pair tables directly --------------------------------------
    // gn(i) = normalized gaussian at patch offset i-P, zero outside [P, P+93)
    #pragma unroll
    for (int i = t; i < GLEN; i += NT) {
        float g0 = 0.0f, g1 = 0.0f;
        const int d0 = i - P, d1 = i + 1 - P;
        if ((unsigned)d0 < (unsigned)KS) {
            const float a = (float)(d0 - KS / 2);
            g0 = __expf(-(a * a) * inv2s2) * invT;
        }
        if ((unsigned)d1 < (unsigned)KS) {
            const float a = (float)(d1 - KS / 2);
            g1 = __expf(-(a * a) * inv2s2) * invT;
        }
        gpair[i] = make_float2(g0, g1);
        gdup[i]  = make_float2(g0, g0);
    }
    __syncthreads();                               // B2: tables ready (last barrier)

    // ---- Warp-local classification of all 256 points ---------------------
    // da = rowBase - R0 in [-3,92]  <-> 4-row window hit  (da3 = da+3 in [0,96))
    // dc = cbw - C0 in [-63,92]     <-> 64-col window hit (dc63 in [0,156))
    int* lst = lists[warp];
    int M = 0;
    const unsigned ltmask = (1u << lane) - 1u;
    #pragma unroll
    for (int r = 0; r < 8; r++) {
        const int da3  = rowBase - (int)truncf(pt[r].x - 46.5f) + 3;
        const int dc63 = cbw     - (int)truncf(pt[r].y - 46.5f) + 63;
        const bool act = ((unsigned)da3  < (unsigned)(KS + RPB - 1)) &&
                         ((unsigned)dc63 < (unsigned)(KS + 63));
        const unsigned bal = __ballot_sync(0xffffffffu, act);
        if (act) lst[M + __popc(bal & ltmask)] = (da3 << 8) | dc63;
        M += __popc(bal);
    }
    __syncwarp();

    // ---- Phase 2: packed f32x2, 4 rows x 2 cols per lane per point -------
    uint64_t acc[RPB];
    #pragma unroll
    for (int r = 0; r < RPB; r++) acc[r] = 0ull;

    #pragma unroll 4
    for (int m = 0; m < M; m++) {
        const int e    = lst[m];                   // broadcast LDS.32
        const int da3  = e >> 8;
        const int dc63 = e & 255;
        // column pair for this lane: index P - 63 + dc63 + 2*lane = 1 + dc63 + 2*lane
        const uint64_t gv2 = *(const uint64_t*)&gpair[1 + dc63 + 2 * lane];
        // row weights (warp-uniform): gdup[P - 3 + da3 + r] = gdup[61 + da3 + r]
        const float2* wd = &gdup[61 + da3];
        #pragma unroll
        for (int r = 0; r < RPB; r++) {
            const uint64_t w2 = *(const uint64_t*)&wd[r];   // LDS.64 broadcast
            asm("fma.rn.f32x2 %0, %1, %2, %0;" : "+l"(acc[r]) : "l"(gv2), "l"(w2));
        }
    }

    // ---- Write 4 rows x 64 cols (2 per lane), STG.64 coalesced ----------
    float* o = out + ((size_t)b * H_OUT + rowBase) * W_OUT + cbw + 2 * lane;
    #pragma unroll
    for (int r = 0; r < RPB; r++) {
        uint32_t lo, hi;
        asm("mov.b64 {%0, %1}, %2;" : "=r"(lo), "=r"(hi) : "l"(acc[r]));
        *(float2*)&o[r * W_OUT] = make_float2(__uint_as_float(lo), __uint_as_float(hi));
    }
}

extern "C" void kernel_launch(void* const* d_in, const int* in_sizes, int n_in,
                              void* d_out, int out_size) {
    // metadata order: [0] batch_images (unused by the math),
    //                 [1] batch_labels [8,256,2] f32, [2] sigma scalar f32
    const float* labels = (const float*)d_in[1];
    const float* sigma  = (const float*)d_in[2];
    float* out = (float*)d_out;                   // [8,1,512,512] f32

    density_kernel<<<8 * (H_OUT / RPB) * 2, NT>>>(labels, sigma, out);
}

// round 12
// speedup vs baseline: 1.1059x; 1.1059x over previous
#include <cuda_runtime.h>
#include <cstdint>

#define KS 93          // gaussian kernel size (static, matches reference)
#define NPTS 256       // points per batch
#define W_OUT 512
#define H_OUT 512
#define RPB 8          // rows per warp tile
#define NT 128         // 4 warps per block; warp w -> 64-col window
#define P 64           // gaussian table base: index for patch offset 0
#define GLEN 220       // table length: nonzero exactly in [P, P+93)

// One block per (batch, 8-row group, 256-col half): grid = 8*64*2 = 1024.
// Warp w owns cols [half*256 + 64w, +64); lane owns 2 adjacent columns.
// Each warp classifies all 256 points itself -> warp-private compact list.
// Only 2 barriers (shared gaussian tables); no cross-warp data flow after.
// Row weights come from gquad[i] = {T[i],T[i],T[i+1],T[i+1]} so one LDS.128
// feeds two packed-row FFMA2s (4 loads for 8 rows instead of 8).
__global__ __launch_bounds__(NT)
void density_kernel(const float* __restrict__ labels,
                    const float* __restrict__ sigma_ptr,
                    float* __restrict__ out) {
    const int half    = blockIdx.x & 1;
    const int rowBase = ((blockIdx.x >> 1) & 63) * RPB;
    const int b       = blockIdx.x >> 7;
    const int t    = threadIdx.x;
    const int warp = t >> 5;
    const int lane = t & 31;
    const int cbw  = half * 256 + warp * 64;      // this warp's column base

    __shared__ __align__(16) float4 gquad[GLEN];  // {T[i],T[i],T[i+1],T[i+1]}
    __shared__ __align__(8)  float2 gpair[GLEN];  // {T[i], T[i+1]}
    __shared__ int   lists[4][NPTS];              // warp-private compact lists
    __shared__ float wsum[3];

    // ---- Prefetch labels (8 points per lane) + sigma ---------------------
    const float2* lab = (const float2*)(labels + (size_t)b * NPTS * 2);
    float2 pt[8];
    #pragma unroll
    for (int r = 0; r < 8; r++) pt[r] = lab[r * 32 + lane];
    const float s = fabsf(sigma_ptr[0]);
    const float inv2s2 = 1.0f / (2.0f * s * s);

    // ---- Gaussian sum (warps 0-2 hold t<96) ------------------------------
    float gval = 0.0f;
    if (t < KS) {
        const float a = (float)(t - KS / 2);      // [-46, 46]
        gval = __expf(-(a * a) * inv2s2);
    }
    if (warp < 3) {
        float v = gval;
        #pragma unroll
        for (int off = 16; off > 0; off >>= 1) v += __shfl_down_sync(0xffffffffu, v, off);
        if (lane == 0) wsum[warp] = v;
    }
    __syncthreads();                               // B1: wsum ready
    const float invT = 1.0f / (wsum[0] + wsum[1] + wsum[2]);

    // ---- Build tables: T[i] = normalized gaussian at offset i-P ----------
    #pragma unroll
    for (int i = t; i < GLEN; i += NT) {
        float g0 = 0.0f, g1 = 0.0f;
        const int d0 = i - P, d1 = i + 1 - P;
        if ((unsigned)d0 < (unsigned)KS) {
            const float a = (float)(d0 - KS / 2);
            g0 = __expf(-(a * a) * inv2s2) * invT;
        }
        if ((unsigned)d1 < (unsigned)KS) {
            const float a = (float)(d1 - KS / 2);
            g1 = __expf(-(a * a) * inv2s2) * invT;
        }
        gpair[i] = make_float2(g0, g1);
        gquad[i] = make_float4(g0, g0, g1, g1);
    }
    __syncthreads();                               // B2: tables ready (last barrier)

    // ---- Warp-local classification of all 256 points ---------------------
    // da = rowBase - R0 in [-7,92]  <-> row window hit  (da7 in [0, 99])
    // dc = cbw - C0 in [-63,92]     <-> col window hit  (dc63 in [0, 155])
    int* lst = lists[warp];
    int M = 0;
    const unsigned ltmask = (1u << lane) - 1u;
    #pragma unroll
    for (int r = 0; r < 8; r++) {
        const int da7  = rowBase - (int)truncf(pt[r].x - 46.5f) + 7;
        const int dc63 = cbw     - (int)truncf(pt[r].y - 46.5f) + 63;
        const bool act = ((unsigned)da7  < (unsigned)(KS + RPB - 1)) &&
                         ((unsigned)dc63 < (unsigned)(KS + 63));
        const unsigned bal = __ballot_sync(0xffffffffu, act);
        if (act) lst[M + __popc(bal & ltmask)] = (da7 << 8) | dc63;
        M += __popc(bal);
    }
    __syncwarp();

    // ---- Phase 2: packed f32x2, 8 rows x 2 cols per lane per point -------
    uint64_t acc[RPB];
    #pragma unroll
    for (int r = 0; r < RPB; r++) acc[r] = 0ull;
    const int lane2 = 2 * lane;

    #pragma unroll 4
    for (int m = 0; m < M; m++) {
        const int e    = lst[m];                   // broadcast LDS.32
        const int da7  = e >> 8;
        const int dc63 = e & 255;
        // column pair for this lane: index P-63 + dc63 + 2*lane = 1 + dc63 + 2*lane
        const uint64_t gv2 = *(const uint64_t*)&gpair[1 + dc63 + lane2];
        // row weights (warp-uniform): rows 2k,2k+1 from one LDS.128
        const float4* wq = &gquad[57 + da7];       // index P-7+da7
        const ulonglong2 q0 = *(const ulonglong2*)&wq[0];
        const ulonglong2 q1 = *(const ulonglong2*)&wq[2];
        const ulonglong2 q2 = *(const ulonglong2*)&wq[4];
        const ulonglong2 q3 = *(const ulonglong2*)&wq[6];
        asm("fma.rn.f32x2 %0, %1, %2, %0;" : "+l"(acc[0]) : "l"(gv2), "l"(q0.x));
        asm("fma.rn.f32x2 %0, %1, %2, %0;" : "+l"(acc[1]) : "l"(gv2), "l"(q0.y));
        asm("fma.rn.f32x2 %0, %1, %2, %0;" : "+l"(acc[2]) : "l"(gv2), "l"(q1.x));
        asm("fma.rn.f32x2 %0, %1, %2, %0;" : "+l"(acc[3]) : "l"(gv2), "l"(q1.y));
        asm("fma.rn.f32x2 %0, %1, %2, %0;" : "+l"(acc[4]) : "l"(gv2), "l"(q2.x));
        asm("fma.rn.f32x2 %0, %1, %2, %0;" : "+l"(acc[5]) : "l"(gv2), "l"(q2.y));
        asm("fma.rn.f32x2 %0, %1, %2, %0;" : "+l"(acc[6]) : "l"(gv2), "l"(q3.x));
        asm("fma.rn.f32x2 %0, %1, %2, %0;" : "+l"(acc[7]) : "l"(gv2), "l"(q3.y));
    }

    // ---- Write 8 rows x 64 cols (2 per lane), STG.64 coalesced ----------
    float* o = out + ((size_t)b * H_OUT + rowBase) * W_OUT + cbw + lane2;
    #pragma unroll
    for (int r = 0; r < RPB; r++) {
        uint32_t lo, hi;
        asm("mov.b64 {%0, %1}, %2;" : "=r"(lo), "=r"(hi) : "l"(acc[r]));
        *(float2*)&o[r * W_OUT] = make_float2(__uint_as_float(lo), __uint_as_float(hi));
    }
}

extern "C" void kernel_launch(void* const* d_in, const int* in_sizes, int n_in,
                              void* d_out, int out_size) {
    // metadata order: [0] batch_images (unused by the math),
    //                 [1] batch_labels [8,256,2] f32, [2] sigma scalar f32
    const float* labels = (const float*)d_in[1];
    const float* sigma  = (const float*)d_in[2];
    float* out = (float*)d_out;                   // [8,1,512,512] f32

    density_kernel<<<8 * (H_OUT / RPB) * 2, NT>>>(labels, sigma, out);
}